// round 8
// baseline (speedup 1.0000x reference)
#include <cuda_runtime.h>
#include <cuda_fp16.h>
#include <cstdint>

#define N_NODES 100000
#define N_EDGES 1600000
#define IN_F 256
#define OUT_F 128

// Device scratch (allocation-free rule: __device__ globals)
__device__ __half g_h[(size_t)N_NODES * OUT_F];       // 25.6 MB (fp16 h)
__device__ int    g_cnt[N_NODES];                      // histogram
__device__ int    g_off[N_NODES + 1];                  // CSR offsets
__device__ int    g_pos[N_NODES];                      // insertion cursors
__device__ int    g_bsum[128];                         // scan block sums
__device__ int2   g_ep[N_EDGES];                       // packed (col, val_bits)

// ---------------------------------------------------------------------------
// GEMM via tf32 tensor cores, cp.async double-buffered: h(fp16) = x @ W + b
// BM=128, BK=32, 256 threads (8 warps as 4Mx2N), warp tile 32x64.
// Smem holds raw fp32 (padded strides 36 / 136 -> conflict-free fragment
// reads); cvt to tf32 happens in the fragment path.
// ---------------------------------------------------------------------------
#define BM 128
#define BK 32
#define A_STR 36            // words per A row
#define B_STR 136           // words per B row
#define A_WORDS (BM * A_STR)            // 4608
#define B_WORDS (BK * B_STR)            // 4352
#define BUF_WORDS (A_WORDS + B_WORDS)   // 8960
#define SMEM_BYTES (2 * BUF_WORDS * 4)  // 71680
#define NT (IN_F / BK)                  // 8 k-tiles

__device__ __forceinline__ uint32_t f2tf32(float f) {
    uint32_t u;
    asm("cvt.rna.tf32.f32 %0, %1;" : "=r"(u) : "f"(f));
    return u;
}

__device__ __forceinline__ void cp_async16(uint32_t dst, const void* src, int src_bytes) {
    asm volatile("cp.async.ca.shared.global [%0], [%1], 16, %2;"
                 :: "r"(dst), "l"(src), "r"(src_bytes));
}
#define CP_COMMIT() asm volatile("cp.async.commit_group;" ::)
#define CP_WAIT(n)  asm volatile("cp.async.wait_group %0;" :: "n"(n))

__global__ __launch_bounds__(256, 2) void gemm_tf32_kernel(
    const float* __restrict__ x,
    const float* __restrict__ W,
    const float* __restrict__ bias,
    __half* __restrict__ h)
{
    extern __shared__ float smem[];
    const uint32_t smem_u32 = (uint32_t)__cvta_generic_to_shared(smem);

    const int tid  = threadIdx.x;
    const int lane = tid & 31;
    const int wid  = tid >> 5;
    const int wm   = wid >> 1;
    const int wn   = wid & 1;
    const int block_row = blockIdx.x * BM;

    // ---- async tile loader: tile kt -> buffer b ----
    auto load_tile = [&](int kt, int b) {
        const int k0 = kt * BK;
        const uint32_t abase = smem_u32 + (uint32_t)(b * BUF_WORDS) * 4u;
        const uint32_t bbase = abase + A_WORDS * 4u;
#pragma unroll
        for (int it = 0; it < 4; it++) {
            int idx   = tid + it * 256;       // 0..1023
            int r     = idx >> 3;             // 0..127
            int chunk = idx & 7;              // 16B chunk within 128B row
            int grow  = block_row + r;
            const float* src = x + (size_t)min(grow, N_NODES - 1) * IN_F + k0 + chunk * 4;
            int nb = (grow < N_NODES) ? 16 : 0;   // zfill OOB rows
            cp_async16(abase + (uint32_t)(r * A_STR) * 4u + (uint32_t)chunk * 16u, src, nb);
        }
#pragma unroll
        for (int it = 0; it < 4; it++) {
            int idx   = tid + it * 256;       // 0..1023
            int kr    = idx >> 5;             // 0..31
            int chunk = idx & 31;             // 16B chunk within 512B row
            const float* src = W + (size_t)(k0 + kr) * OUT_F + chunk * 4;
            cp_async16(bbase + (uint32_t)(kr * B_STR) * 4u + (uint32_t)chunk * 16u, src, 16);
        }
    };

    float acc[2][8][4];
#pragma unroll
    for (int mi = 0; mi < 2; mi++)
#pragma unroll
        for (int ni = 0; ni < 8; ni++)
#pragma unroll
            for (int q = 0; q < 4; q++) acc[mi][ni][q] = 0.0f;

    // Prologue: prefetch tiles 0 and 1
    load_tile(0, 0); CP_COMMIT();
    load_tile(1, 1); CP_COMMIT();

#pragma unroll
    for (int kt = 0; kt < NT; kt++) {
        if (kt < NT - 1) { CP_WAIT(1); } else { CP_WAIT(0); }
        __syncthreads();

        const float* Asb = smem + (kt & 1) * BUF_WORDS;
        const float* Bsb = Asb + A_WORDS;

#pragma unroll
        for (int ks = 0; ks < BK; ks += 8) {
            uint32_t af[2][4], bf[8][2];
#pragma unroll
            for (int mi = 0; mi < 2; mi++) {
                int r = wm * 32 + mi * 16 + (lane >> 2);
                int c = ks + (lane & 3);
                af[mi][0] = f2tf32(Asb[r * A_STR + c]);
                af[mi][1] = f2tf32(Asb[(r + 8) * A_STR + c]);
                af[mi][2] = f2tf32(Asb[r * A_STR + c + 4]);
                af[mi][3] = f2tf32(Asb[(r + 8) * A_STR + c + 4]);
            }
#pragma unroll
            for (int ni = 0; ni < 8; ni++) {
                int col = wn * 64 + ni * 8 + (lane >> 2);
                bf[ni][0] = f2tf32(Bsb[(ks + (lane & 3)) * B_STR + col]);
                bf[ni][1] = f2tf32(Bsb[(ks + (lane & 3) + 4) * B_STR + col]);
            }
#pragma unroll
            for (int mi = 0; mi < 2; mi++)
#pragma unroll
                for (int ni = 0; ni < 8; ni++) {
                    asm volatile(
                        "mma.sync.aligned.m16n8k8.row.col.f32.tf32.tf32.f32 "
                        "{%0,%1,%2,%3}, {%4,%5,%6,%7}, {%8,%9}, {%0,%1,%2,%3};"
                        : "+f"(acc[mi][ni][0]), "+f"(acc[mi][ni][1]),
                          "+f"(acc[mi][ni][2]), "+f"(acc[mi][ni][3])
                        : "r"(af[mi][0]), "r"(af[mi][1]),
                          "r"(af[mi][2]), "r"(af[mi][3]),
                          "r"(bf[ni][0]), "r"(bf[ni][1]));
                }
        }
        __syncthreads();   // all warps done reading buf (kt&1) before refill

        if (kt + 2 < NT) { load_tile(kt + 2, kt & 1); CP_COMMIT(); }
    }

    // Epilogue: bias + fp16 store (pairs c0,c1 at row r; c2,c3 at row r+8)
#pragma unroll
    for (int mi = 0; mi < 2; mi++) {
        int r0 = block_row + wm * 32 + mi * 16 + (lane >> 2);
#pragma unroll
        for (int ni = 0; ni < 8; ni++) {
            int col = wn * 64 + ni * 8 + 2 * (lane & 3);
            float b0 = bias[col], b1 = bias[col + 1];
            if (r0 < N_NODES) {
                __half2 p = __floats2half2_rn(acc[mi][ni][0] + b0,
                                              acc[mi][ni][1] + b1);
                *(__half2*)(h + (size_t)r0 * OUT_F + col) = p;
            }
            if (r0 + 8 < N_NODES) {
                __half2 p = __floats2half2_rn(acc[mi][ni][2] + b0,
                                              acc[mi][ni][3] + b1);
                *(__half2*)(h + (size_t)(r0 + 8) * OUT_F + col) = p;
            }
        }
    }
}

// ---------------------------------------------------------------------------
// CSR construction: histogram -> scan -> reorder (vectorized edge reads)
// ---------------------------------------------------------------------------
__global__ void hist_kernel(const int4* __restrict__ rows4, int* __restrict__ cnt, int E4)
{
    int i = blockIdx.x * blockDim.x + threadIdx.x;
    int stride = gridDim.x * blockDim.x;
    for (; i < E4; i += stride) {
        int4 r = rows4[i];
        asm volatile("red.global.add.u32 [%0], %1;" :: "l"(cnt + r.x), "r"(1) : "memory");
        asm volatile("red.global.add.u32 [%0], %1;" :: "l"(cnt + r.y), "r"(1) : "memory");
        asm volatile("red.global.add.u32 [%0], %1;" :: "l"(cnt + r.z), "r"(1) : "memory");
        asm volatile("red.global.add.u32 [%0], %1;" :: "l"(cnt + r.w), "r"(1) : "memory");
    }
}

__global__ __launch_bounds__(256) void scan1_kernel(
    const int* __restrict__ cnt, int* __restrict__ pre,
    int* __restrict__ bsum, int n)
{
    __shared__ int s[256];
    const int tid = threadIdx.x;
    int base = blockIdx.x * 1024 + tid * 4;
    int v[4]; int sum = 0;
#pragma unroll
    for (int i = 0; i < 4; i++) {
        v[i] = (base + i < n) ? cnt[base + i] : 0;
        sum += v[i];
    }
    s[tid] = sum;
    __syncthreads();
#pragma unroll
    for (int off = 1; off < 256; off <<= 1) {
        int t = (tid >= off) ? s[tid - off] : 0;
        __syncthreads();
        s[tid] += t;
        __syncthreads();
    }
    int running = (tid == 0) ? 0 : s[tid - 1];
#pragma unroll
    for (int i = 0; i < 4; i++) {
        if (base + i < n) pre[base + i] = running;
        running += v[i];
    }
    if (tid == 255) bsum[blockIdx.x] = s[255];
}

__global__ __launch_bounds__(128) void scan2_kernel(int* __restrict__ bsum, int nb)
{
    __shared__ int s[128];
    const int tid = threadIdx.x;
    int v = (tid < nb) ? bsum[tid] : 0;
    s[tid] = v;
    __syncthreads();
#pragma unroll
    for (int off = 1; off < 128; off <<= 1) {
        int t = (tid >= off) ? s[tid - off] : 0;
        __syncthreads();
        s[tid] += t;
        __syncthreads();
    }
    if (tid < nb) bsum[tid] = (tid == 0) ? 0 : s[tid - 1];
}

__global__ void scan3_kernel(int* __restrict__ off, int* __restrict__ pos,
                             const int* __restrict__ bsum, int n, int E)
{
    int i = blockIdx.x * blockDim.x + threadIdx.x;
    int stride = gridDim.x * blockDim.x;
    for (; i < n; i += stride) {
        int o = off[i] + bsum[i >> 10];
        off[i] = o;
        pos[i] = o;
    }
    if (blockIdx.x == 0 && threadIdx.x == 0) off[n] = E;
}

__global__ void reorder_kernel(
    const int4*   __restrict__ rows4,
    const int4*   __restrict__ cols4,
    const float4* __restrict__ vals4,
    int*          __restrict__ pos,
    int2*         __restrict__ ep,
    int E4)
{
    int i = blockIdx.x * blockDim.x + threadIdx.x;
    int stride = gridDim.x * blockDim.x;
    for (; i < E4; i += stride) {
        int4   r = rows4[i];
        int4   c = cols4[i];
        float4 v = vals4[i];
        int p0 = atomicAdd(pos + r.x, 1); ep[p0] = make_int2(c.x, __float_as_int(v.x));
        int p1 = atomicAdd(pos + r.y, 1); ep[p1] = make_int2(c.y, __float_as_int(v.y));
        int p2 = atomicAdd(pos + r.z, 1); ep[p2] = make_int2(c.z, __float_as_int(v.z));
        int p3 = atomicAdd(pos + r.w, 1); ep[p3] = make_int2(c.w, __float_as_int(v.w));
    }
}

// ---------------------------------------------------------------------------
// Aggregate: one warp per destination node. fp16 h gather (8B/lane),
// fp32 accumulation, single float4 store. No atomics.
// ---------------------------------------------------------------------------
__global__ __launch_bounds__(256) void aggregate_kernel(
    const int*    __restrict__ off,
    const int2*   __restrict__ ep,
    const __half* __restrict__ h,
    float*        __restrict__ out)
{
    const int lane = threadIdx.x & 31;
    const int node = blockIdx.x * 8 + (threadIdx.x >> 5);
    if (node >= N_NODES) return;

    int s = off[node];
    int e = off[node + 1];

    float4 acc = make_float4(0.f, 0.f, 0.f, 0.f);
    int i = s;

#define GATHER_ONE(CC, VV)                                                   \
    {                                                                        \
        const uint2 raw = *(const uint2*)(h + (size_t)(CC) * OUT_F + lane * 4); \
        float2 lo = __half22float2(*(const __half2*)&raw.x);                 \
        float2 hi = __half22float2(*(const __half2*)&raw.y);                 \
        acc.x = fmaf((VV), lo.x, acc.x);                                     \
        acc.y = fmaf((VV), lo.y, acc.y);                                     \
        acc.z = fmaf((VV), hi.x, acc.z);                                     \
        acc.w = fmaf((VV), hi.y, acc.w);                                     \
    }

    for (; i + 3 < e; i += 4) {
        int2 p0 = ep[i],     p1 = ep[i + 1];
        int2 p2 = ep[i + 2], p3 = ep[i + 3];
        GATHER_ONE(p0.x, __int_as_float(p0.y));
        GATHER_ONE(p1.x, __int_as_float(p1.y));
        GATHER_ONE(p2.x, __int_as_float(p2.y));
        GATHER_ONE(p3.x, __int_as_float(p3.y));
    }
    for (; i < e; i++) {
        int2 p = ep[i];
        GATHER_ONE(p.x, __int_as_float(p.y));
    }
#undef GATHER_ONE

    *(float4*)(out + (size_t)node * OUT_F + lane * 4) = acc;
}

// ---------------------------------------------------------------------------
extern "C" void kernel_launch(void* const* d_in, const int* in_sizes, int n_in,
                              void* d_out, int out_size)
{
    const float* x    = (const float*)d_in[0];
    const int*   erow = (const int*)  d_in[1];
    const int*   ecol = (const int*)  d_in[2];
    const float* eval = (const float*)d_in[3];
    const float* W    = (const float*)d_in[4];
    const float* bias = (const float*)d_in[5];
    float* out = (float*)d_out;

    __half* h;    cudaGetSymbolAddress((void**)&h, g_h);
    int*    cnt;  cudaGetSymbolAddress((void**)&cnt, g_cnt);
    int*    off;  cudaGetSymbolAddress((void**)&off, g_off);
    int*    pos;  cudaGetSymbolAddress((void**)&pos, g_pos);
    int*    bsum; cudaGetSymbolAddress((void**)&bsum, g_bsum);
    int2*   ep;   cudaGetSymbolAddress((void**)&ep, g_ep);

    const int NBLK_SCAN = (N_NODES + 1023) / 1024;  // 98
    const int E4 = N_EDGES / 4;

    cudaFuncSetAttribute(gemm_tf32_kernel,
                         cudaFuncAttributeMaxDynamicSharedMemorySize, SMEM_BYTES);

    // GEMM on tensor cores (fp16 h output), cp.async double-buffered
    gemm_tf32_kernel<<<(N_NODES + BM - 1) / BM, 256, SMEM_BYTES>>>(x, W, bias, h);

    // CSR build (independent of GEMM result)
    cudaMemsetAsync(cnt, 0, N_NODES * sizeof(int), 0);
    hist_kernel<<<1184, 256>>>((const int4*)erow, cnt, E4);
    scan1_kernel<<<NBLK_SCAN, 256>>>(cnt, off, bsum, N_NODES);
    scan2_kernel<<<1, 128>>>(bsum, NBLK_SCAN);
    scan3_kernel<<<98, 256>>>(off, pos, bsum, N_NODES, N_EDGES);
    reorder_kernel<<<1184, 256>>>((const int4*)erow, (const int4*)ecol,
                                  (const float4*)eval, pos, ep, E4);

    // Per-node aggregation (no atomics)
    aggregate_kernel<<<(N_NODES + 7) / 8, 256>>>(off, ep, h, out);
}

// round 11
// speedup vs baseline: 1.4139x; 1.4139x over previous
#include <cuda_runtime.h>
#include <cuda_fp16.h>
#include <cstdint>

#define N_NODES 100000
#define N_EDGES 1600000
#define IN_F 256
#define OUT_F 128

// Device scratch (allocation-free rule: __device__ globals)
__device__ __half g_h[(size_t)N_NODES * OUT_F];       // 25.6 MB (fp16 h)
__device__ int    g_cnt[N_NODES];                      // histogram
__device__ int    g_off[N_NODES + 1];                  // CSR offsets
__device__ int    g_pos[N_NODES];                      // insertion cursors
__device__ int    g_bsum[128];                         // scan block sums
__device__ int2   g_ep[N_EDGES];                       // packed (col, val_bits)

// ---------------------------------------------------------------------------
// GEMM via tf32 tensor cores, cp.async double-buffered: h(fp16) = x @ W + b
// Smem holds RAW fp32 (padded strides 36/136 -> conflict-free fragment reads).
// tf32 rounding in the fragment path is done with an integer add (+0x1000):
// bit-identical to cvt.rna.tf32 after HMMA truncates the low 13 mantissa
// bits, but costs one IADD3 (alu pipe, rt=2) instead of a slow F2FP.
// ---------------------------------------------------------------------------
#define BM 128
#define BK 32
#define A_STR 36            // words per A row
#define B_STR 136           // words per B row
#define A_WORDS (BM * A_STR)            // 4608
#define B_WORDS (BK * B_STR)            // 4352
#define BUF_WORDS (A_WORDS + B_WORDS)   // 8960
#define SMEM_BYTES (2 * BUF_WORDS * 4)  // 71680
#define NT (IN_F / BK)                  // 8 k-tiles

__device__ __forceinline__ uint32_t rtf32(float f) {
    // round-to-nearest(-away) into the tf32 bit positions; HMMA ignores the
    // low 13 mantissa bits, so this is bit-identical to cvt.rna.tf32.f32.
    return __float_as_uint(f) + 0x1000u;
}

__device__ __forceinline__ void cp_async16(uint32_t dst, const void* src, int src_bytes) {
    asm volatile("cp.async.ca.shared.global [%0], [%1], 16, %2;"
                 :: "r"(dst), "l"(src), "r"(src_bytes));
}
#define CP_COMMIT() asm volatile("cp.async.commit_group;" ::)
#define CP_WAIT(n)  asm volatile("cp.async.wait_group %0;" :: "n"(n))

__global__ __launch_bounds__(256, 2) void gemm_tf32_kernel(
    const float* __restrict__ x,
    const float* __restrict__ W,
    const float* __restrict__ bias,
    __half* __restrict__ h)
{
    extern __shared__ float smem[];
    const uint32_t smem_u32 = (uint32_t)__cvta_generic_to_shared(smem);

    const int tid  = threadIdx.x;
    const int lane = tid & 31;
    const int wid  = tid >> 5;
    const int wm   = wid >> 1;
    const int wn   = wid & 1;
    const int block_row = blockIdx.x * BM;

    auto load_tile = [&](int kt, int b) {
        const int k0 = kt * BK;
        const uint32_t abase = smem_u32 + (uint32_t)(b * BUF_WORDS) * 4u;
        const uint32_t bbase = abase + A_WORDS * 4u;
#pragma unroll
        for (int it = 0; it < 4; it++) {
            int idx   = tid + it * 256;       // 0..1023
            int r     = idx >> 3;             // 0..127
            int chunk = idx & 7;              // 16B chunk within 128B row
            int grow  = block_row + r;
            const float* src = x + (size_t)min(grow, N_NODES - 1) * IN_F + k0 + chunk * 4;
            int nb = (grow < N_NODES) ? 16 : 0;   // zfill OOB rows
            cp_async16(abase + (uint32_t)(r * A_STR) * 4u + (uint32_t)chunk * 16u, src, nb);
        }
#pragma unroll
        for (int it = 0; it < 4; it++) {
            int idx   = tid + it * 256;       // 0..1023
            int kr    = idx >> 5;             // 0..31
            int chunk = idx & 31;             // 16B chunk within 512B row
            const float* src = W + (size_t)(k0 + kr) * OUT_F + chunk * 4;
            cp_async16(bbase + (uint32_t)(kr * B_STR) * 4u + (uint32_t)chunk * 16u, src, 16);
        }
    };

    float acc[2][8][4];
#pragma unroll
    for (int mi = 0; mi < 2; mi++)
#pragma unroll
        for (int ni = 0; ni < 8; ni++)
#pragma unroll
            for (int q = 0; q < 4; q++) acc[mi][ni][q] = 0.0f;

    // Prologue: prefetch tiles 0 and 1
    load_tile(0, 0); CP_COMMIT();
    load_tile(1, 1); CP_COMMIT();

#pragma unroll
    for (int kt = 0; kt < NT; kt++) {
        if (kt < NT - 1) { CP_WAIT(1); } else { CP_WAIT(0); }
        __syncthreads();

        const float* Asb = smem + (kt & 1) * BUF_WORDS;
        const float* Bsb = Asb + A_WORDS;

#pragma unroll
        for (int ks = 0; ks < BK; ks += 8) {
            uint32_t af[2][4], bf[8][2];
#pragma unroll
            for (int mi = 0; mi < 2; mi++) {
                int r = wm * 32 + mi * 16 + (lane >> 2);
                int c = ks + (lane & 3);
                af[mi][0] = rtf32(Asb[r * A_STR + c]);
                af[mi][1] = rtf32(Asb[(r + 8) * A_STR + c]);
                af[mi][2] = rtf32(Asb[r * A_STR + c + 4]);
                af[mi][3] = rtf32(Asb[(r + 8) * A_STR + c + 4]);
            }
#pragma unroll
            for (int ni = 0; ni < 8; ni++) {
                int col = wn * 64 + ni * 8 + (lane >> 2);
                bf[ni][0] = rtf32(Bsb[(ks + (lane & 3)) * B_STR + col]);
                bf[ni][1] = rtf32(Bsb[(ks + (lane & 3) + 4) * B_STR + col]);
            }
#pragma unroll
            for (int mi = 0; mi < 2; mi++)
#pragma unroll
                for (int ni = 0; ni < 8; ni++) {
                    asm volatile(
                        "mma.sync.aligned.m16n8k8.row.col.f32.tf32.tf32.f32 "
                        "{%0,%1,%2,%3}, {%4,%5,%6,%7}, {%8,%9}, {%0,%1,%2,%3};"
                        : "+f"(acc[mi][ni][0]), "+f"(acc[mi][ni][1]),
                          "+f"(acc[mi][ni][2]), "+f"(acc[mi][ni][3])
                        : "r"(af[mi][0]), "r"(af[mi][1]),
                          "r"(af[mi][2]), "r"(af[mi][3]),
                          "r"(bf[ni][0]), "r"(bf[ni][1]));
                }
        }
        __syncthreads();   // all warps done reading buf (kt&1) before refill

        if (kt + 2 < NT) { load_tile(kt + 2, kt & 1); CP_COMMIT(); }
    }

    // Epilogue: bias + fp16 store (pairs c0,c1 at row r; c2,c3 at row r+8)
#pragma unroll
    for (int mi = 0; mi < 2; mi++) {
        int r0 = block_row + wm * 32 + mi * 16 + (lane >> 2);
#pragma unroll
        for (int ni = 0; ni < 8; ni++) {
            int col = wn * 64 + ni * 8 + 2 * (lane & 3);
            float b0 = bias[col], b1 = bias[col + 1];
            if (r0 < N_NODES) {
                __half2 p = __floats2half2_rn(acc[mi][ni][0] + b0,
                                              acc[mi][ni][1] + b1);
                *(__half2*)(h + (size_t)r0 * OUT_F + col) = p;
            }
            if (r0 + 8 < N_NODES) {
                __half2 p = __floats2half2_rn(acc[mi][ni][2] + b0,
                                              acc[mi][ni][3] + b1);
                *(__half2*)(h + (size_t)(r0 + 8) * OUT_F + col) = p;
            }
        }
    }
}

// ---------------------------------------------------------------------------
// CSR construction: histogram -> scan (2 kernels) -> reorder
// ---------------------------------------------------------------------------
__global__ void hist_kernel(const int4* __restrict__ rows4, int* __restrict__ cnt, int E4)
{
    int i = blockIdx.x * blockDim.x + threadIdx.x;
    int stride = gridDim.x * blockDim.x;
    for (; i < E4; i += stride) {
        int4 r = rows4[i];
        asm volatile("red.global.add.u32 [%0], %1;" :: "l"(cnt + r.x), "r"(1) : "memory");
        asm volatile("red.global.add.u32 [%0], %1;" :: "l"(cnt + r.y), "r"(1) : "memory");
        asm volatile("red.global.add.u32 [%0], %1;" :: "l"(cnt + r.z), "r"(1) : "memory");
        asm volatile("red.global.add.u32 [%0], %1;" :: "l"(cnt + r.w), "r"(1) : "memory");
    }
}

// scan1: per-block (1024 elems) local exclusive scan + block sum
__global__ __launch_bounds__(256) void scan1_kernel(
    const int* __restrict__ cnt, int* __restrict__ pre,
    int* __restrict__ bsum, int n)
{
    __shared__ int s[256];
    const int tid = threadIdx.x;
    int base = blockIdx.x * 1024 + tid * 4;
    int v[4]; int sum = 0;
#pragma unroll
    for (int i = 0; i < 4; i++) {
        v[i] = (base + i < n) ? cnt[base + i] : 0;
        sum += v[i];
    }
    s[tid] = sum;
    __syncthreads();
#pragma unroll
    for (int off = 1; off < 256; off <<= 1) {
        int t = (tid >= off) ? s[tid - off] : 0;
        __syncthreads();
        s[tid] += t;
        __syncthreads();
    }
    int running = (tid == 0) ? 0 : s[tid - 1];
#pragma unroll
    for (int i = 0; i < 4; i++) {
        if (base + i < n) pre[base + i] = running;
        running += v[i];
    }
    if (tid == 255) bsum[blockIdx.x] = s[255];
}

// scan23: fused. Block bid reduces bsum[0..bid) in-smem (98 entries, cheap),
// then adds it to its 1024 contiguous elements. Removes the scan2 launch.
__global__ __launch_bounds__(256) void scan23_kernel(
    int* __restrict__ off, int* __restrict__ pos,
    const int* __restrict__ bsum, int n, int E, int nb)
{
    __shared__ int red[256];
    const int tid = threadIdx.x;
    const int bid = blockIdx.x;

    red[tid] = (tid < nb && tid < bid) ? bsum[tid] : 0;
    __syncthreads();
#pragma unroll
    for (int o = 128; o > 0; o >>= 1) {
        if (tid < o) red[tid] += red[tid + o];
        __syncthreads();
    }
    const int base_off = red[0];

    int base = bid * 1024 + tid * 4;
#pragma unroll
    for (int i = 0; i < 4; i++) {
        int idx = base + i;
        if (idx < n) {
            int o = off[idx] + base_off;
            off[idx] = o;
            pos[idx] = o;
        }
    }
    if (bid == nb - 1 && tid == 0) off[n] = E;
}

__global__ void reorder_kernel(
    const int4*   __restrict__ rows4,
    const int4*   __restrict__ cols4,
    const float4* __restrict__ vals4,
    int*          __restrict__ pos,
    int2*         __restrict__ ep,
    int E4)
{
    int i = blockIdx.x * blockDim.x + threadIdx.x;
    int stride = gridDim.x * blockDim.x;
    for (; i < E4; i += stride) {
        int4   r = rows4[i];
        int4   c = cols4[i];
        float4 v = vals4[i];
        int p0 = atomicAdd(pos + r.x, 1); ep[p0] = make_int2(c.x, __float_as_int(v.x));
        int p1 = atomicAdd(pos + r.y, 1); ep[p1] = make_int2(c.y, __float_as_int(v.y));
        int p2 = atomicAdd(pos + r.z, 1); ep[p2] = make_int2(c.z, __float_as_int(v.z));
        int p3 = atomicAdd(pos + r.w, 1); ep[p3] = make_int2(c.w, __float_as_int(v.w));
    }
}

// ---------------------------------------------------------------------------
// Aggregate: one warp per destination node. fp16 h gather (8B/lane),
// fp32 accumulation, single float4 store. No atomics.
// ---------------------------------------------------------------------------
__global__ __launch_bounds__(256) void aggregate_kernel(
    const int*    __restrict__ off,
    const int2*   __restrict__ ep,
    const __half* __restrict__ h,
    float*        __restrict__ out)
{
    const int lane = threadIdx.x & 31;
    const int node = blockIdx.x * 8 + (threadIdx.x >> 5);
    if (node >= N_NODES) return;

    int s = off[node];
    int e = off[node + 1];

    float4 acc = make_float4(0.f, 0.f, 0.f, 0.f);
    int i = s;

#define GATHER_ONE(CC, VV)                                                   \
    {                                                                        \
        const uint2 raw = *(const uint2*)(h + (size_t)(CC) * OUT_F + lane * 4); \
        float2 lo = __half22float2(*(const __half2*)&raw.x);                 \
        float2 hi = __half22float2(*(const __half2*)&raw.y);                 \
        acc.x = fmaf((VV), lo.x, acc.x);                                     \
        acc.y = fmaf((VV), lo.y, acc.y);                                     \
        acc.z = fmaf((VV), hi.x, acc.z);                                     \
        acc.w = fmaf((VV), hi.y, acc.w);                                     \
    }

    for (; i + 3 < e; i += 4) {
        int2 p0 = ep[i],     p1 = ep[i + 1];
        int2 p2 = ep[i + 2], p3 = ep[i + 3];
        GATHER_ONE(p0.x, __int_as_float(p0.y));
        GATHER_ONE(p1.x, __int_as_float(p1.y));
        GATHER_ONE(p2.x, __int_as_float(p2.y));
        GATHER_ONE(p3.x, __int_as_float(p3.y));
    }
    for (; i < e; i++) {
        int2 p = ep[i];
        GATHER_ONE(p.x, __int_as_float(p.y));
    }
#undef GATHER_ONE

    *(float4*)(out + (size_t)node * OUT_F + lane * 4) = acc;
}

// ---------------------------------------------------------------------------
extern "C" void kernel_launch(void* const* d_in, const int* in_sizes, int n_in,
                              void* d_out, int out_size)
{
    const float* x    = (const float*)d_in[0];
    const int*   erow = (const int*)  d_in[1];
    const int*   ecol = (const int*)  d_in[2];
    const float* eval = (const float*)d_in[3];
    const float* W    = (const float*)d_in[4];
    const float* bias = (const float*)d_in[5];
    float* out = (float*)d_out;

    __half* h;    cudaGetSymbolAddress((void**)&h, g_h);
    int*    cnt;  cudaGetSymbolAddress((void**)&cnt, g_cnt);
    int*    off;  cudaGetSymbolAddress((void**)&off, g_off);
    int*    pos;  cudaGetSymbolAddress((void**)&pos, g_pos);
    int*    bsum; cudaGetSymbolAddress((void**)&bsum, g_bsum);
    int2*   ep;   cudaGetSymbolAddress((void**)&ep, g_ep);

    const int NBLK_SCAN = (N_NODES + 1023) / 1024;  // 98
    const int E4 = N_EDGES / 4;

    cudaFuncSetAttribute(gemm_tf32_kernel,
                         cudaFuncAttributeMaxDynamicSharedMemorySize, SMEM_BYTES);

    // GEMM on tensor cores (fp16 h output), cp.async double-buffered,
    // tf32 rounding via integer add in the fragment path
    gemm_tf32_kernel<<<(N_NODES + BM - 1) / BM, 256, SMEM_BYTES>>>(x, W, bias, h);

    // CSR build (independent of GEMM result)
    cudaMemsetAsync(cnt, 0, N_NODES * sizeof(int), 0);
    hist_kernel<<<1184, 256>>>((const int4*)erow, cnt, E4);
    scan1_kernel<<<NBLK_SCAN, 256>>>(cnt, off, bsum, N_NODES);
    scan23_kernel<<<NBLK_SCAN, 256>>>(off, pos, bsum, N_NODES, N_EDGES, NBLK_SCAN);
    reorder_kernel<<<1184, 256>>>((const int4*)erow, (const int4*)ecol,
                                  (const float4*)eval, pos, ep, E4);

    // Per-node aggregation (no atomics)
    aggregate_kernel<<<(N_NODES + 7) / 8, 256>>>(off, ep, h, out);
}

// round 13
// speedup vs baseline: 1.5013x; 1.0618x over previous
#include <cuda_runtime.h>
#include <cuda_fp16.h>
#include <cstdint>

#define N_NODES 100000
#define N_EDGES 1600000
#define IN_F 256
#define OUT_F 128

// Device scratch (allocation-free rule: __device__ globals)
__device__ __half g_h[(size_t)N_NODES * OUT_F];       // 25.6 MB (fp16 h)
__device__ int    g_cnt[N_NODES];                      // histogram
__device__ int    g_off[N_NODES + 1];                  // CSR offsets
__device__ int    g_pos[N_NODES];                      // insertion cursors
__device__ int    g_bsum[128];                         // scan block sums
__device__ int2   g_ep[N_EDGES];                       // packed (col, val_bits)

// ---------------------------------------------------------------------------
// GEMM via tf32 tensor cores, cp.async double-buffered: h(fp16) = x @ W + b
// Smem holds RAW fp32 (padded strides 36/136 -> conflict-free fragment reads).
// tf32 rounding in the fragment path via integer add (+0x1000): bit-identical
// to cvt.rna.tf32 after HMMA truncates the low 13 mantissa bits.
// ---------------------------------------------------------------------------
#define BM 128
#define BK 32
#define A_STR 36            // words per A row
#define B_STR 136           // words per B row
#define A_WORDS (BM * A_STR)            // 4608
#define B_WORDS (BK * B_STR)            // 4352
#define BUF_WORDS (A_WORDS + B_WORDS)   // 8960
#define SMEM_BYTES (2 * BUF_WORDS * 4)  // 71680
#define NT (IN_F / BK)                  // 8 k-tiles

__device__ __forceinline__ uint32_t rtf32(float f) {
    return __float_as_uint(f) + 0x1000u;
}

__device__ __forceinline__ void cp_async16(uint32_t dst, const void* src, int src_bytes) {
    asm volatile("cp.async.ca.shared.global [%0], [%1], 16, %2;"
                 :: "r"(dst), "l"(src), "r"(src_bytes));
}
#define CP_COMMIT() asm volatile("cp.async.commit_group;" ::)
#define CP_WAIT(n)  asm volatile("cp.async.wait_group %0;" :: "n"(n))

__global__ __launch_bounds__(256, 2) void gemm_tf32_kernel(
    const float* __restrict__ x,
    const float* __restrict__ W,
    const float* __restrict__ bias,
    __half* __restrict__ h)
{
    extern __shared__ float smem[];
    const uint32_t smem_u32 = (uint32_t)__cvta_generic_to_shared(smem);

    const int tid  = threadIdx.x;
    const int lane = tid & 31;
    const int wid  = tid >> 5;
    const int wm   = wid >> 1;
    const int wn   = wid & 1;
    const int block_row = blockIdx.x * BM;

    auto load_tile = [&](int kt, int b) {
        const int k0 = kt * BK;
        const uint32_t abase = smem_u32 + (uint32_t)(b * BUF_WORDS) * 4u;
        const uint32_t bbase = abase + A_WORDS * 4u;
#pragma unroll
        for (int it = 0; it < 4; it++) {
            int idx   = tid + it * 256;       // 0..1023
            int r     = idx >> 3;             // 0..127
            int chunk = idx & 7;              // 16B chunk within 128B row
            int grow  = block_row + r;
            const float* src = x + (size_t)min(grow, N_NODES - 1) * IN_F + k0 + chunk * 4;
            int nb = (grow < N_NODES) ? 16 : 0;   // zfill OOB rows
            cp_async16(abase + (uint32_t)(r * A_STR) * 4u + (uint32_t)chunk * 16u, src, nb);
        }
#pragma unroll
        for (int it = 0; it < 4; it++) {
            int idx   = tid + it * 256;       // 0..1023
            int kr    = idx >> 5;             // 0..31
            int chunk = idx & 31;             // 16B chunk within 512B row
            const float* src = W + (size_t)(k0 + kr) * OUT_F + chunk * 4;
            cp_async16(bbase + (uint32_t)(kr * B_STR) * 4u + (uint32_t)chunk * 16u, src, 16);
        }
    };

    float acc[2][8][4];
#pragma unroll
    for (int mi = 0; mi < 2; mi++)
#pragma unroll
        for (int ni = 0; ni < 8; ni++)
#pragma unroll
            for (int q = 0; q < 4; q++) acc[mi][ni][q] = 0.0f;

    load_tile(0, 0); CP_COMMIT();
    load_tile(1, 1); CP_COMMIT();

#pragma unroll
    for (int kt = 0; kt < NT; kt++) {
        if (kt < NT - 1) { CP_WAIT(1); } else { CP_WAIT(0); }
        __syncthreads();

        const float* Asb = smem + (kt & 1) * BUF_WORDS;
        const float* Bsb = Asb + A_WORDS;

#pragma unroll
        for (int ks = 0; ks < BK; ks += 8) {
            uint32_t af[2][4], bf[8][2];
#pragma unroll
            for (int mi = 0; mi < 2; mi++) {
                int r = wm * 32 + mi * 16 + (lane >> 2);
                int c = ks + (lane & 3);
                af[mi][0] = rtf32(Asb[r * A_STR + c]);
                af[mi][1] = rtf32(Asb[(r + 8) * A_STR + c]);
                af[mi][2] = rtf32(Asb[r * A_STR + c + 4]);
                af[mi][3] = rtf32(Asb[(r + 8) * A_STR + c + 4]);
            }
#pragma unroll
            for (int ni = 0; ni < 8; ni++) {
                int col = wn * 64 + ni * 8 + (lane >> 2);
                bf[ni][0] = rtf32(Bsb[(ks + (lane & 3)) * B_STR + col]);
                bf[ni][1] = rtf32(Bsb[(ks + (lane & 3) + 4) * B_STR + col]);
            }
#pragma unroll
            for (int mi = 0; mi < 2; mi++)
#pragma unroll
                for (int ni = 0; ni < 8; ni++) {
                    asm volatile(
                        "mma.sync.aligned.m16n8k8.row.col.f32.tf32.tf32.f32 "
                        "{%0,%1,%2,%3}, {%4,%5,%6,%7}, {%8,%9}, {%0,%1,%2,%3};"
                        : "+f"(acc[mi][ni][0]), "+f"(acc[mi][ni][1]),
                          "+f"(acc[mi][ni][2]), "+f"(acc[mi][ni][3])
                        : "r"(af[mi][0]), "r"(af[mi][1]),
                          "r"(af[mi][2]), "r"(af[mi][3]),
                          "r"(bf[ni][0]), "r"(bf[ni][1]));
                }
        }
        __syncthreads();

        if (kt + 2 < NT) { load_tile(kt + 2, kt & 1); CP_COMMIT(); }
    }

#pragma unroll
    for (int mi = 0; mi < 2; mi++) {
        int r0 = block_row + wm * 32 + mi * 16 + (lane >> 2);
#pragma unroll
        for (int ni = 0; ni < 8; ni++) {
            int col = wn * 64 + ni * 8 + 2 * (lane & 3);
            float b0 = bias[col], b1 = bias[col + 1];
            if (r0 < N_NODES) {
                __half2 p = __floats2half2_rn(acc[mi][ni][0] + b0,
                                              acc[mi][ni][1] + b1);
                *(__half2*)(h + (size_t)r0 * OUT_F + col) = p;
            }
            if (r0 + 8 < N_NODES) {
                __half2 p = __floats2half2_rn(acc[mi][ni][2] + b0,
                                              acc[mi][ni][3] + b1);
                *(__half2*)(h + (size_t)(r0 + 8) * OUT_F + col) = p;
            }
        }
    }
}

// ---------------------------------------------------------------------------
// CSR construction: histogram -> scan -> reorder
// ---------------------------------------------------------------------------
__global__ void hist_kernel(const int4* __restrict__ rows4, int* __restrict__ cnt, int E4)
{
    int i = blockIdx.x * blockDim.x + threadIdx.x;
    int stride = gridDim.x * blockDim.x;
    for (; i < E4; i += stride) {
        int4 r = rows4[i];
        asm volatile("red.global.add.u32 [%0], %1;" :: "l"(cnt + r.x), "r"(1) : "memory");
        asm volatile("red.global.add.u32 [%0], %1;" :: "l"(cnt + r.y), "r"(1) : "memory");
        asm volatile("red.global.add.u32 [%0], %1;" :: "l"(cnt + r.z), "r"(1) : "memory");
        asm volatile("red.global.add.u32 [%0], %1;" :: "l"(cnt + r.w), "r"(1) : "memory");
    }
}

__global__ __launch_bounds__(256) void scan1_kernel(
    const int* __restrict__ cnt, int* __restrict__ pre,
    int* __restrict__ bsum, int n)
{
    __shared__ int s[256];
    const int tid = threadIdx.x;
    int base = blockIdx.x * 1024 + tid * 4;
    int v[4]; int sum = 0;
#pragma unroll
    for (int i = 0; i < 4; i++) {
        v[i] = (base + i < n) ? cnt[base + i] : 0;
        sum += v[i];
    }
    s[tid] = sum;
    __syncthreads();
#pragma unroll
    for (int off = 1; off < 256; off <<= 1) {
        int t = (tid >= off) ? s[tid - off] : 0;
        __syncthreads();
        s[tid] += t;
        __syncthreads();
    }
    int running = (tid == 0) ? 0 : s[tid - 1];
#pragma unroll
    for (int i = 0; i < 4; i++) {
        if (base + i < n) pre[base + i] = running;
        running += v[i];
    }
    if (tid == 255) bsum[blockIdx.x] = s[255];
}

// scan23: fused. Block bid reduces bsum[0..bid) in-smem, then adds to its
// 1024 contiguous elements.
__global__ __launch_bounds__(256) void scan23_kernel(
    int* __restrict__ off, int* __restrict__ pos,
    const int* __restrict__ bsum, int n, int E, int nb)
{
    __shared__ int red[256];
    const int tid = threadIdx.x;
    const int bid = blockIdx.x;

    red[tid] = (tid < nb && tid < bid) ? bsum[tid] : 0;
    __syncthreads();
#pragma unroll
    for (int o = 128; o > 0; o >>= 1) {
        if (tid < o) red[tid] += red[tid + o];
        __syncthreads();
    }
    const int base_off = red[0];

    int base = bid * 1024 + tid * 4;
#pragma unroll
    for (int i = 0; i < 4; i++) {
        int idx = base + i;
        if (idx < n) {
            int o = off[idx] + base_off;
            off[idx] = o;
            pos[idx] = o;
        }
    }
    if (bid == nb - 1 && tid == 0) off[n] = E;
}

__global__ void reorder_kernel(
    const int4*   __restrict__ rows4,
    const int4*   __restrict__ cols4,
    const float4* __restrict__ vals4,
    int*          __restrict__ pos,
    int2*         __restrict__ ep,
    int E4)
{
    int i = blockIdx.x * blockDim.x + threadIdx.x;
    int stride = gridDim.x * blockDim.x;
    for (; i < E4; i += stride) {
        int4   r = rows4[i];
        int4   c = cols4[i];
        float4 v = vals4[i];
        int p0 = atomicAdd(pos + r.x, 1); ep[p0] = make_int2(c.x, __float_as_int(v.x));
        int p1 = atomicAdd(pos + r.y, 1); ep[p1] = make_int2(c.y, __float_as_int(v.y));
        int p2 = atomicAdd(pos + r.z, 1); ep[p2] = make_int2(c.z, __float_as_int(v.z));
        int p3 = atomicAdd(pos + r.w, 1); ep[p3] = make_int2(c.w, __float_as_int(v.w));
    }
}

// ---------------------------------------------------------------------------
// Aggregate: one warp per destination node. fp16 h gather (8B/lane),
// fp32 accumulation, single float4 store. No atomics.
// ---------------------------------------------------------------------------
__global__ __launch_bounds__(256) void aggregate_kernel(
    const int*    __restrict__ off,
    const int2*   __restrict__ ep,
    const __half* __restrict__ h,
    float*        __restrict__ out)
{
    const int lane = threadIdx.x & 31;
    const int node = blockIdx.x * 8 + (threadIdx.x >> 5);
    if (node >= N_NODES) return;

    int s = off[node];
    int e = off[node + 1];

    float4 acc = make_float4(0.f, 0.f, 0.f, 0.f);
    int i = s;

#define GATHER_ONE(CC, VV)                                                   \
    {                                                                        \
        const uint2 raw = *(const uint2*)(h + (size_t)(CC) * OUT_F + lane * 4); \
        float2 lo = __half22float2(*(const __half2*)&raw.x);                 \
        float2 hi = __half22float2(*(const __half2*)&raw.y);                 \
        acc.x = fmaf((VV), lo.x, acc.x);                                     \
        acc.y = fmaf((VV), lo.y, acc.y);                                     \
        acc.z = fmaf((VV), hi.x, acc.z);                                     \
        acc.w = fmaf((VV), hi.y, acc.w);                                     \
    }

    for (; i + 3 < e; i += 4) {
        int2 p0 = ep[i],     p1 = ep[i + 1];
        int2 p2 = ep[i + 2], p3 = ep[i + 3];
        GATHER_ONE(p0.x, __int_as_float(p0.y));
        GATHER_ONE(p1.x, __int_as_float(p1.y));
        GATHER_ONE(p2.x, __int_as_float(p2.y));
        GATHER_ONE(p3.x, __int_as_float(p3.y));
    }
    for (; i < e; i++) {
        int2 p = ep[i];
        GATHER_ONE(p.x, __int_as_float(p.y));
    }
#undef GATHER_ONE

    *(float4*)(out + (size_t)node * OUT_F + lane * 4) = acc;
}

// ---------------------------------------------------------------------------
// Launch: fork the independent CSR branch onto a second stream so the graph
// runs {GEMM} || {memset->hist->scan1->scan23->reorder}, joining at aggregate.
// Stream/events are created once (host infra, not device memory, not work).
// ---------------------------------------------------------------------------
struct AuxStreams {
    cudaStream_t s2;
    cudaEvent_t  ev_fork, ev_join;
    AuxStreams() {
        cudaStreamCreateWithFlags(&s2, cudaStreamNonBlocking);
        cudaEventCreateWithFlags(&ev_fork, cudaEventDisableTiming);
        cudaEventCreateWithFlags(&ev_join, cudaEventDisableTiming);
    }
};

extern "C" void kernel_launch(void* const* d_in, const int* in_sizes, int n_in,
                              void* d_out, int out_size)
{
    const float* x    = (const float*)d_in[0];
    const int*   erow = (const int*)  d_in[1];
    const int*   ecol = (const int*)  d_in[2];
    const float* eval = (const float*)d_in[3];
    const float* W    = (const float*)d_in[4];
    const float* bias = (const float*)d_in[5];
    float* out = (float*)d_out;

    __half* h;    cudaGetSymbolAddress((void**)&h, g_h);
    int*    cnt;  cudaGetSymbolAddress((void**)&cnt, g_cnt);
    int*    off;  cudaGetSymbolAddress((void**)&off, g_off);
    int*    pos;  cudaGetSymbolAddress((void**)&pos, g_pos);
    int*    bsum; cudaGetSymbolAddress((void**)&bsum, g_bsum);
    int2*   ep;   cudaGetSymbolAddress((void**)&ep, g_ep);

    static AuxStreams aux;   // created on first call; work per call is identical

    const int NBLK_SCAN = (N_NODES + 1023) / 1024;  // 98
    const int E4 = N_EDGES / 4;

    cudaFuncSetAttribute(gemm_tf32_kernel,
                         cudaFuncAttributeMaxDynamicSharedMemorySize, SMEM_BYTES);

    // ---- fork: branch B (CSR build) runs on aux.s2 ----
    cudaEventRecord(aux.ev_fork, 0);
    cudaStreamWaitEvent(aux.s2, aux.ev_fork, 0);

    // Branch A (stream 0): GEMM on tensor cores (fp16 h output)
    gemm_tf32_kernel<<<(N_NODES + BM - 1) / BM, 256, SMEM_BYTES>>>(x, W, bias, h);

    // Branch B (stream s2): CSR build — touches only edge arrays
    cudaMemsetAsync(cnt, 0, N_NODES * sizeof(int), aux.s2);
    hist_kernel<<<1184, 256, 0, aux.s2>>>((const int4*)erow, cnt, E4);
    scan1_kernel<<<NBLK_SCAN, 256, 0, aux.s2>>>(cnt, off, bsum, N_NODES);
    scan23_kernel<<<NBLK_SCAN, 256, 0, aux.s2>>>(off, pos, bsum, N_NODES, N_EDGES, NBLK_SCAN);
    reorder_kernel<<<1184, 256, 0, aux.s2>>>((const int4*)erow, (const int4*)ecol,
                                             (const float4*)eval, pos, ep, E4);

    // ---- join: aggregate needs both h (stream 0) and ep/off (s2) ----
    cudaEventRecord(aux.ev_join, aux.s2);
    cudaStreamWaitEvent(0, aux.ev_join, 0);

    aggregate_kernel<<<(N_NODES + 7) / 8, 256>>>(off, ep, h, out);
}